// round 1
// baseline (speedup 1.0000x reference)
#include <cuda_runtime.h>
#include <math.h>

// ---------------------------------------------------------------------------
// GAT layer, fp32 SIMT baseline (round 0)
//   d_in: 0 feat[50000,128] 1 src[640000] 2 dst[640000] 3 Wq 4 Wk 5 Wv (128x128)
//         6 ln1_g[128] 7 ln1_b[128] 8 W1[128,512] 9 b1[512] 10 prelu_a[512]
//         11 W2[512,128] 12 b2[128]
//   out: [50000,128] f32
// Pipeline:
//   CSR build (hist -> scan -> scatter)  |  QKV gemm
//   aggregate: warp/node online softmax over incoming edges + residual + LN1
//   FFN1 gemm (+bias+PReLU) ; FFN2 gemm (+bias+residual+LN)
// ---------------------------------------------------------------------------

#define NNODES 50000
#define NEDGES 640000
#define FDIM   128
#define DFF    512
#define SCAN_NB ((NNODES + 255) / 256)   // 196

// scratch (static device globals; no runtime allocation allowed)
__device__ __align__(16) float g_q[NNODES * FDIM];
__device__ __align__(16) float g_k[NNODES * FDIM];
__device__ __align__(16) float g_v[NNODES * FDIM];
__device__ __align__(16) float g_rst[NNODES * FDIM];
__device__ __align__(16) float g_hbuf[NNODES * DFF];
__device__ int g_deg[NNODES];
__device__ int g_off[NNODES + 1];
__device__ int g_eid[NEDGES];
__device__ int g_bsum[256];

// ---------------------------------------------------------------- CSR build
__global__ void k_zero_deg() {
    int i = blockIdx.x * blockDim.x + threadIdx.x;
    if (i < NNODES) g_deg[i] = 0;
}

__global__ void k_hist(const int* __restrict__ dst) {
    int e = blockIdx.x * blockDim.x + threadIdx.x;
    if (e < NEDGES) atomicAdd(&g_deg[dst[e]], 1);
}

__global__ void k_scan1() {
    __shared__ int s[256];
    int b = blockIdx.x, t = threadIdx.x;
    int i = b * 256 + t;
    int v = (i < NNODES) ? g_deg[i] : 0;
    s[t] = v;
    __syncthreads();
#pragma unroll
    for (int off = 1; off < 256; off <<= 1) {
        int add = (t >= off) ? s[t - off] : 0;
        __syncthreads();
        s[t] += add;
        __syncthreads();
    }
    if (i < NNODES) g_off[i + 1] = s[t];
    if (t == 255) g_bsum[b] = s[t];
}

__global__ void k_scan2() {
    __shared__ int s[256];
    int t = threadIdx.x;
    int v = (t < SCAN_NB) ? g_bsum[t] : 0;
    s[t] = v;
    __syncthreads();
#pragma unroll
    for (int off = 1; off < 256; off <<= 1) {
        int add = (t >= off) ? s[t - off] : 0;
        __syncthreads();
        s[t] += add;
        __syncthreads();
    }
    if (t < SCAN_NB) g_bsum[t] = s[t] - v;   // exclusive
}

__global__ void k_scan3() {
    int b = blockIdx.x, t = threadIdx.x;
    int i = b * 256 + t;
    if (i < NNODES) g_off[i + 1] += g_bsum[b];
    if (i == 0) g_off[0] = 0;
}

__global__ void k_scatter(const int* __restrict__ dst) {
    int e = blockIdx.x * blockDim.x + threadIdx.x;
    if (e < NEDGES) {
        int d = dst[e];
        int pos = g_off[d] + atomicAdd(&g_deg[d], 1);
        g_eid[pos] = e;
    }
}

// ---------------------------------------------------------------- GEMMs
// tile: BM=64, BN=128, BK=16; 256 threads; thread tile 8x4
// tx = tid&31 (col quad), ty = tid>>5 (row octet)

#define GEMM_MAINLOOP(Aptr, Bptr, KTOT, LDB, COL0)                              \
    float acc[8][4];                                                            \
    _Pragma("unroll") for (int i = 0; i < 8; i++)                               \
        _Pragma("unroll") for (int j = 0; j < 4; j++) acc[i][j] = 0.f;          \
    __shared__ float As[16][64];                                                \
    __shared__ float4 Bs[16][32];                                               \
    const int tid = threadIdx.x;                                                \
    const int tx = tid & 31, ty = tid >> 5;                                     \
    const int row0 = blockIdx.y * 64;                                           \
    for (int k0 = 0; k0 < (KTOT); k0 += 16) {                                   \
        {                                                                       \
            int r = tid >> 2, kq = tid & 3;                                     \
            float4 av = make_float4(0.f, 0.f, 0.f, 0.f);                        \
            if (row0 + r < NNODES)                                              \
                av = *(const float4*)((Aptr) + (size_t)(row0 + r) * (KTOT) +    \
                                      k0 + kq * 4);                             \
            As[kq * 4 + 0][r] = av.x;                                           \
            As[kq * 4 + 1][r] = av.y;                                           \
            As[kq * 4 + 2][r] = av.z;                                           \
            As[kq * 4 + 3][r] = av.w;                                           \
        }                                                                       \
        _Pragma("unroll") for (int it = 0; it < 2; ++it) {                      \
            int idx = it * 256 + tid;                                           \
            int kk = idx >> 5, c4 = idx & 31;                                   \
            Bs[kk][c4] = *(const float4*)((Bptr) + (size_t)(k0 + kk) * (LDB) +  \
                                          (COL0) + c4 * 4);                     \
        }                                                                       \
        __syncthreads();                                                        \
        _Pragma("unroll") for (int kk = 0; kk < 16; ++kk) {                     \
            float4 bq = Bs[kk][tx];                                             \
            _Pragma("unroll") for (int i = 0; i < 8; i++) {                     \
                float a = As[kk][ty * 8 + i];                                   \
                acc[i][0] += a * bq.x;                                          \
                acc[i][1] += a * bq.y;                                          \
                acc[i][2] += a * bq.z;                                          \
                acc[i][3] += a * bq.w;                                          \
            }                                                                   \
        }                                                                       \
        __syncthreads();                                                        \
    }

// QKV: grid (3, 782). blockIdx.x selects {Wq->g_q, Wk->g_k, Wv->g_v}
__global__ __launch_bounds__(256) void k_gemm_qkv(
    const float* __restrict__ feat, const float* __restrict__ Wq,
    const float* __restrict__ Wk, const float* __restrict__ Wv) {
    const int m = blockIdx.x;
    const float* B = (m == 0) ? Wq : (m == 1) ? Wk : Wv;
    float* C = (m == 0) ? g_q : (m == 1) ? g_k : g_v;
    GEMM_MAINLOOP(feat, B, FDIM, FDIM, 0)
#pragma unroll
    for (int i = 0; i < 8; i++) {
        int row = row0 + ty * 8 + i;
        if (row < NNODES) {
            float4 o = make_float4(acc[i][0], acc[i][1], acc[i][2], acc[i][3]);
            *(float4*)(C + (size_t)row * FDIM + tx * 4) = o;
        }
    }
}

// FFN1: C = PReLU(rst @ W1 + b1) -> g_hbuf ; grid (4, 782)
__global__ __launch_bounds__(256) void k_ffn1(
    const float* __restrict__ W1, const float* __restrict__ b1,
    const float* __restrict__ pa) {
    const int col0 = blockIdx.x * 128;
    GEMM_MAINLOOP(g_rst, W1, FDIM, DFF, col0)
    const int c = col0 + tx * 4;
    float4 bv = *(const float4*)(b1 + c);
    float4 av = *(const float4*)(pa + c);
#pragma unroll
    for (int i = 0; i < 8; i++) {
        int row = row0 + ty * 8 + i;
        if (row < NNODES) {
            float h0 = acc[i][0] + bv.x;
            float h1 = acc[i][1] + bv.y;
            float h2 = acc[i][2] + bv.z;
            float h3 = acc[i][3] + bv.w;
            h0 = (h0 >= 0.f) ? h0 : av.x * h0;
            h1 = (h1 >= 0.f) ? h1 : av.y * h1;
            h2 = (h2 >= 0.f) ? h2 : av.z * h2;
            h3 = (h3 >= 0.f) ? h3 : av.w * h3;
            *(float4*)(g_hbuf + (size_t)row * DFF + c) =
                make_float4(h0, h1, h2, h3);
        }
    }
}

// FFN2: out = LN(rst + h @ W2 + b2) ; grid (1, 782). Full row (128) per warp.
__global__ __launch_bounds__(256) void k_ffn2(
    const float* __restrict__ W2, const float* __restrict__ b2,
    const float* __restrict__ lng, const float* __restrict__ lnb,
    float* __restrict__ out) {
    GEMM_MAINLOOP(g_hbuf, W2, DFF, FDIM, 0)
    const int c = tx * 4;
    float4 bv = *(const float4*)(b2 + c);
    float4 gv = *(const float4*)(lng + c);
    float4 lb = *(const float4*)(lnb + c);
#pragma unroll
    for (int i = 0; i < 8; i++) {
        int row = row0 + ty * 8 + i;
        if (row >= NNODES) continue;   // warp-uniform (row indep of lane)
        float4 rv = *(const float4*)(g_rst + (size_t)row * FDIM + c);
        float x0 = acc[i][0] + bv.x + rv.x;
        float x1 = acc[i][1] + bv.y + rv.y;
        float x2 = acc[i][2] + bv.z + rv.z;
        float x3 = acc[i][3] + bv.w + rv.w;
        float p = x0 + x1 + x2 + x3;
#pragma unroll
        for (int o = 16; o; o >>= 1) p += __shfl_xor_sync(0xffffffffu, p, o);
        float mu = p * (1.f / 128.f);
        float d0 = x0 - mu, d1 = x1 - mu, d2 = x2 - mu, d3 = x3 - mu;
        float q = d0 * d0 + d1 * d1 + d2 * d2 + d3 * d3;
#pragma unroll
        for (int o = 16; o; o >>= 1) q += __shfl_xor_sync(0xffffffffu, q, o);
        float rs = rsqrtf(q * (1.f / 128.f) + 1e-5f);
        float4 y = make_float4(d0 * rs * gv.x + lb.x, d1 * rs * gv.y + lb.y,
                               d2 * rs * gv.z + lb.z, d3 * rs * gv.w + lb.w);
        *(float4*)(out + (size_t)row * FDIM + c) = y;
    }
}

// --------------------------------------------- attention aggregate + LN1
// one warp per dst node; online softmax per head over incoming edges.
// lane l owns dims [4l,4l+4) => head h = l>>2 (quad-local reduction).
__global__ __launch_bounds__(256) void k_aggregate(
    const float* __restrict__ feat, const int* __restrict__ src,
    const float* __restrict__ lng, const float* __restrict__ lnb) {
    int n = (blockIdx.x * blockDim.x + threadIdx.x) >> 5;
    int lane = threadIdx.x & 31;
    if (n >= NNODES) return;

    const float4 q4 = *(const float4*)(g_q + (size_t)n * FDIM + lane * 4);
    float4 acc = make_float4(0.f, 0.f, 0.f, 0.f);
    float m = -INFINITY, s = 0.f;
    const float rscale = 0.08838834764831845f;   // 1/sqrt(128)

    int beg = g_off[n], end = g_off[n + 1];
    for (int idx = beg; idx < end; ++idx) {
        int e = g_eid[idx];
        int sn = src[e];
        const float4 k4 = *(const float4*)(g_k + (size_t)sn * FDIM + lane * 4);
        const float4 v4 = *(const float4*)(g_v + (size_t)sn * FDIM + lane * 4);
        float p = k4.x * q4.x + k4.y * q4.y + k4.z * q4.z + k4.w * q4.w;
        p += __shfl_xor_sync(0xffffffffu, p, 1);
        p += __shfl_xor_sync(0xffffffffu, p, 2);   // quad = one head
        float eh = p * rscale;
        float mn = fmaxf(m, eh);
        float corr = __expf(m - mn);   // m=-inf first iter -> corr=0
        float wgt = __expf(eh - mn);
        s = s * corr + wgt;
        acc.x = acc.x * corr + v4.x * wgt;
        acc.y = acc.y * corr + v4.y * wgt;
        acc.z = acc.z * corr + v4.z * wgt;
        acc.w = acc.w * corr + v4.w * wgt;
        m = mn;
    }
    float inv = (s > 0.f) ? 1.f / s : 0.f;

    const float4 f4 = *(const float4*)(feat + (size_t)n * FDIM + lane * 4);
    float x0 = acc.x * inv + f4.x;
    float x1 = acc.y * inv + f4.y;
    float x2 = acc.z * inv + f4.z;
    float x3 = acc.w * inv + f4.w;

    float p = x0 + x1 + x2 + x3;
#pragma unroll
    for (int o = 16; o; o >>= 1) p += __shfl_xor_sync(0xffffffffu, p, o);
    float mu = p * (1.f / 128.f);
    float d0 = x0 - mu, d1 = x1 - mu, d2 = x2 - mu, d3 = x3 - mu;
    float q = d0 * d0 + d1 * d1 + d2 * d2 + d3 * d3;
#pragma unroll
    for (int o = 16; o; o >>= 1) q += __shfl_xor_sync(0xffffffffu, q, o);
    float rs = rsqrtf(q * (1.f / 128.f) + 1e-5f);

    const float4 gv = *(const float4*)(lng + lane * 4);
    const float4 lb = *(const float4*)(lnb + lane * 4);
    float4 y = make_float4(d0 * rs * gv.x + lb.x, d1 * rs * gv.y + lb.y,
                           d2 * rs * gv.z + lb.z, d3 * rs * gv.w + lb.w);
    *(float4*)(g_rst + (size_t)n * FDIM + lane * 4) = y;
}

// ---------------------------------------------------------------- launch
extern "C" void kernel_launch(void* const* d_in, const int* in_sizes, int n_in,
                              void* d_out, int out_size) {
    const float* feat = (const float*)d_in[0];
    const int* src = (const int*)d_in[1];
    const int* dst = (const int*)d_in[2];
    const float* Wq = (const float*)d_in[3];
    const float* Wk = (const float*)d_in[4];
    const float* Wv = (const float*)d_in[5];
    const float* ln1_g = (const float*)d_in[6];
    const float* ln1_b = (const float*)d_in[7];
    const float* W1 = (const float*)d_in[8];
    const float* b1 = (const float*)d_in[9];
    const float* pa = (const float*)d_in[10];
    const float* W2 = (const float*)d_in[11];
    const float* b2 = (const float*)d_in[12];
    float* out = (float*)d_out;

    const int MB = (NNODES + 63) / 64;   // 782

    // CSR build
    k_zero_deg<<<SCAN_NB, 256>>>();
    k_hist<<<NEDGES / 256, 256>>>(dst);
    k_scan1<<<SCAN_NB, 256>>>();
    k_scan2<<<1, 256>>>();
    k_scan3<<<SCAN_NB, 256>>>();
    k_zero_deg<<<SCAN_NB, 256>>>();
    k_scatter<<<NEDGES / 256, 256>>>(dst);

    // projections
    k_gemm_qkv<<<dim3(3, MB), 256>>>(feat, Wq, Wk, Wv);

    // attention aggregation + residual + LN1
    k_aggregate<<<(NNODES * 32 + 255) / 256, 256>>>(feat, src, ln1_g, ln1_b);

    // FFN
    k_ffn1<<<dim3(DFF / 128, MB), 256>>>(W1, b1, pa);
    k_ffn2<<<dim3(1, MB), 256>>>(W2, b2, ln1_g, ln1_b, out);
}